// round 10
// baseline (speedup 1.0000x reference)
#include <cuda_runtime.h>

#define NN 50000
#define NE 800000
#define NET (NE + NN)
#define HEADS 4
#define HID 64
#define D1 256            // HEADS*HID
#define IND 128
#define EMB 128
#define NG 64
#define SPLIT 25088       // 196 * 128, node-range split for agg1/gemm2 pipeline

typedef unsigned long long ull;

// ---------------- scratch ----------------
__device__ __align__(16) float g_h1[(size_t)NN * D1];
__device__ __align__(16) float g_act1[(size_t)NN * D1];
__device__ __align__(16) float g_h2[(size_t)NN * EMB];
__device__ __align__(16) float g_as1[NN * HEADS];
__device__ __align__(16) float g_ad1[NN * HEADS];
__device__ __align__(16) float g_as2[NN];
__device__ __align__(16) float g_ad2[NN];
__device__ __align__(16) float g_pool[NG * EMB];
__device__ __align__(16) float g_cnt[NG];
__device__ __align__(16) int   g_src[NET];
__device__ __align__(16) int   g_dst[NET];
__device__ __align__(16) int   g_batch[NN];
__device__ __align__(16) int   g_rowptr[NN + 1];
__device__ __align__(16) int   g_wp[NN];
__device__ __align__(16) int   g_csrc[NET];

// ---------------- helpers ----------------
__device__ __forceinline__ float elu1(float x)  { return x > 0.f ? x : expm1f(x); }
__device__ __forceinline__ float lrelu(float x) { return x > 0.f ? x : 0.2f * x; }

__device__ __forceinline__ void red4(float* p, float a, float b, float c, float d) {
    asm volatile("red.global.add.v4.f32 [%0], {%1, %2, %3, %4};"
                 :: "l"(p), "f"(a), "f"(b), "f"(c), "f"(d) : "memory");
}
__device__ __forceinline__ void ffma2(ull& d, ull a, ull b) {
    asm("fma.rn.f32x2 %0, %1, %2, %0;" : "+l"(d) : "l"(a), "l"(b));
}
__device__ __forceinline__ ull pack2(float lo, float hi) {
    ull r; asm("mov.b64 %0, {%1, %2};" : "=l"(r) : "f"(lo), "f"(hi)); return r;
}
__device__ __forceinline__ void unpack2(float& lo, float& hi, ull v) {
    asm("mov.b64 {%0, %1}, %2;" : "=f"(lo), "=f"(hi) : "l"(v));
}

// ---------------- prep / CSR ----------------
__global__ __launch_bounds__(256) void prep_kernel(const void* ei_raw, const void* b_raw) {
    const int*       e32 = (const int*)ei_raw;
    const long long* e64 = (const long long*)ei_raw;
    bool is64 = true;
#pragma unroll
    for (int i = 0; i < 16; i++) is64 &= (e32[2 * i + 1] == 0);

    int idx = blockIdx.x * blockDim.x + threadIdx.x;
    if (idx < NET) {
        int s, d;
        if (idx < NE) {
            if (is64) { s = (int)e64[idx]; d = (int)e64[NE + idx]; }
            else      { s = e32[idx];      d = e32[NE + idx]; }
        } else { s = d = idx - NE; }
        g_src[idx] = s;
        g_dst[idx] = d;
    }
    if (idx < NN) {
        g_batch[idx] = is64 ? (int)((const long long*)b_raw)[idx] : ((const int*)b_raw)[idx];
        g_wp[idx] = 0;
    }
    if (idx < NG * EMB) g_pool[idx] = 0.f;
    if (idx < NG)       g_cnt[idx]  = 0.f;
}

__global__ __launch_bounds__(256) void deg_kernel() {
    int idx = blockIdx.x * blockDim.x + threadIdx.x;
    if (idx < NET) atomicAdd(&g_wp[g_dst[idx]], 1);
    if (idx < NN)  atomicAdd(&g_cnt[g_batch[idx]], 1.f);
}

__global__ __launch_bounds__(1024) void scan_kernel() {
    __shared__ int part[1024];
    int t = threadIdx.x;
    const int CH = (NN + 1023) / 1024;
    int beg = t * CH, end = min(beg + CH, NN);
    int sum = 0;
    for (int i = beg; i < end; i++) sum += g_wp[i];
    part[t] = sum;
    __syncthreads();
    for (int off = 1; off < 1024; off <<= 1) {
        int v = (t >= off) ? part[t - off] : 0;
        __syncthreads();
        part[t] += v;
        __syncthreads();
    }
    int run = (t == 0) ? 0 : part[t - 1];
    for (int i = beg; i < end; i++) {
        int c = g_wp[i];
        g_rowptr[i] = run;
        g_wp[i] = run;
        run += c;
    }
    if (t == 1023) g_rowptr[NN] = run;
}

__global__ __launch_bounds__(256) void fill_kernel() {
    int e = blockIdx.x * blockDim.x + threadIdx.x;
    if (e >= NET) return;
    int pos = atomicAdd(&g_wp[g_dst[e]], 1);
    g_csrc[pos] = g_src[e];
}

// ---------------- f32x2 GEMM + fused attention-dot epilogue ----------------
// C[M,N] = A[M,K] @ B[K,N]. BM=128, BN=128, BK=8, 256 threads, 8x8/thread.
// Accumulators paired along N: acc[i][j] = (row ty*8+i, cols tx*8+2j, +2j+1).
// B pairs come free from LDS.128 reinterpret; only A needs (a,a) duplication.
__global__ __launch_bounds__(256, 2) void gemm_kernel(
    const float* __restrict__ A, const float* __restrict__ B, float* __restrict__ C,
    int M, int N, int K, int rowOff,
    const float* __restrict__ avec, const float* __restrict__ dvec,
    float* __restrict__ as_out, float* __restrict__ ad_out, int multihead)
{
    __shared__ float As[8][132];
    __shared__ float Bs[8][132];

    int tid = threadIdx.x;
    int lane = tid & 31;
    int rowBase = rowOff + blockIdx.x * 128;
    int colBase = blockIdx.y * 128;
    int tx = tid & 15;
    int ty = tid >> 4;

    ull acc[8][4];
#pragma unroll
    for (int i = 0; i < 8; i++)
#pragma unroll
        for (int j = 0; j < 4; j++) acc[i][j] = 0ull;

    int arow = rowBase + (tid >> 1);
    int akoff = (tid & 1) * 4;
    int brow = tid >> 5;
    int bcol = colBase + (tid & 31) * 4;
    int r = tid >> 1;

    for (int k0 = 0; k0 < K; k0 += 8) {
        float4 av = make_float4(0.f, 0.f, 0.f, 0.f);
        if (arow < M) av = *(const float4*)(A + (long long)arow * K + k0 + akoff);
        float4 bv = *(const float4*)(B + (long long)(k0 + brow) * N + bcol);
        As[akoff + 0][r] = av.x; As[akoff + 1][r] = av.y;
        As[akoff + 2][r] = av.z; As[akoff + 3][r] = av.w;
        *(float4*)&Bs[brow][(tid & 31) * 4] = bv;
        __syncthreads();
#pragma unroll
        for (int kk = 0; kk < 8; kk++) {
            float4 af0 = *(const float4*)&As[kk][ty * 8];
            float4 af1 = *(const float4*)&As[kk][ty * 8 + 4];
            ulonglong2 b01 = *(const ulonglong2*)&Bs[kk][tx * 8];
            ulonglong2 b23 = *(const ulonglong2*)&Bs[kk][tx * 8 + 4];
            ull rb[4] = {b01.x, b01.y, b23.x, b23.y};
            ull ra[8];
            ra[0] = pack2(af0.x, af0.x); ra[1] = pack2(af0.y, af0.y);
            ra[2] = pack2(af0.z, af0.z); ra[3] = pack2(af0.w, af0.w);
            ra[4] = pack2(af1.x, af1.x); ra[5] = pack2(af1.y, af1.y);
            ra[6] = pack2(af1.z, af1.z); ra[7] = pack2(af1.w, af1.w);
#pragma unroll
            for (int i = 0; i < 8; i++)
#pragma unroll
                for (int j = 0; j < 4; j++) ffma2(acc[i][j], ra[i], rb[j]);
        }
        __syncthreads();
    }

    // ---- epilogue: store C + fused attention dots (FFMA2 pairs) ----
    float4 av0 = *(const float4*)(avec + colBase + tx * 8);
    float4 av1 = *(const float4*)(avec + colBase + tx * 8 + 4);
    float4 dv0 = *(const float4*)(dvec + colBase + tx * 8);
    float4 dv1 = *(const float4*)(dvec + colBase + tx * 8 + 4);
    ull avp[4] = {pack2(av0.x, av0.y), pack2(av0.z, av0.w),
                  pack2(av1.x, av1.y), pack2(av1.z, av1.w)};
    ull dvp[4] = {pack2(dv0.x, dv0.y), pack2(dv0.z, dv0.w),
                  pack2(dv1.x, dv1.y), pack2(dv1.z, dv1.w)};
    float ds[8], dd[8];

#pragma unroll
    for (int i = 0; i < 8; i++) {
        int row = rowBase + ty * 8 + i;
        ull s2 = 0ull, d2 = 0ull;
#pragma unroll
        for (int j = 0; j < 4; j++) {
            ffma2(s2, acc[i][j], avp[j]);
            ffma2(d2, acc[i][j], dvp[j]);
        }
        float slo, shi, dlo, dhi;
        unpack2(slo, shi, s2);
        unpack2(dlo, dhi, d2);
        ds[i] = slo + shi;
        dd[i] = dlo + dhi;
        if (row < M) {
            long long cbase = (long long)row * N + colBase + tx * 8;
            *(ulonglong2*)(C + cbase)     = make_ulonglong2(acc[i][0], acc[i][1]);
            *(ulonglong2*)(C + cbase + 4) = make_ulonglong2(acc[i][2], acc[i][3]);
        }
    }
#pragma unroll
    for (int rr = 0; rr < 8; rr++) {
        ds[rr] += __shfl_xor_sync(0xffffffffu, ds[rr], 1);
        ds[rr] += __shfl_xor_sync(0xffffffffu, ds[rr], 2);
        ds[rr] += __shfl_xor_sync(0xffffffffu, ds[rr], 4);
        dd[rr] += __shfl_xor_sync(0xffffffffu, dd[rr], 1);
        dd[rr] += __shfl_xor_sync(0xffffffffu, dd[rr], 2);
        dd[rr] += __shfl_xor_sync(0xffffffffu, dd[rr], 4);
        if (!multihead) {
            ds[rr] += __shfl_xor_sync(0xffffffffu, ds[rr], 8);
            dd[rr] += __shfl_xor_sync(0xffffffffu, dd[rr], 8);
        }
    }
    int rowb = rowBase + ty * 8;
    if (multihead) {
        if ((lane & 7) == 0) {
            int head = (colBase >> 6) + ((lane >> 3) & 1);
#pragma unroll
            for (int rr = 0; rr < 8; rr++) {
                int row = rowb + rr;
                if (row < M) {
                    as_out[row * 4 + head] = ds[rr];
                    ad_out[row * 4 + head] = dd[rr];
                }
            }
        }
    } else {
        if ((lane & 15) == 0) {
#pragma unroll
            for (int rr = 0; rr < 8; rr++) {
                int row = rowb + rr;
                if (row < M) {
                    as_out[row] = ds[rr];
                    ad_out[row] = dd[rr];
                }
            }
        }
    }
}

// ---------------- CSR aggregation (warp per dst node, node-range) ----------------
__global__ __launch_bounds__(256) void agg1_kernel(const float* __restrict__ b1,
                                                   int nodeOff, int nodeEnd) {
    int d = nodeOff + ((blockIdx.x * blockDim.x + threadIdx.x) >> 5);
    int lane = threadIdx.x & 31;
    if (d >= nodeEnd) return;
    int h = lane >> 3;
    float ad = g_ad1[d * 4 + h];
    int beg = g_rowptr[d], end = g_rowptr[d + 1];
    float z = 0.f;
    float4 a0 = make_float4(0.f, 0.f, 0.f, 0.f);
    float4 a1 = make_float4(0.f, 0.f, 0.f, 0.f);
    for (int i = beg; i < end; i++) {
        int s = g_csrc[i];
        float w = __expf(lrelu(g_as1[s * 4 + h] + ad));
        z += w;
        const float4* hp = (const float4*)(g_h1 + (long long)s * D1);
        float4 v0 = hp[lane * 2], v1 = hp[lane * 2 + 1];
        a0.x += w * v0.x; a0.y += w * v0.y; a0.z += w * v0.z; a0.w += w * v0.w;
        a1.x += w * v1.x; a1.y += w * v1.y; a1.z += w * v1.z; a1.w += w * v1.w;
    }
    float inv = 1.f / z;
    const float4* bb = (const float4*)(b1 + lane * 8);
    float4 c0 = bb[0], c1 = bb[1];
    float4 o0, o1;
    o0.x = elu1(a0.x * inv + c0.x); o0.y = elu1(a0.y * inv + c0.y);
    o0.z = elu1(a0.z * inv + c0.z); o0.w = elu1(a0.w * inv + c0.w);
    o1.x = elu1(a1.x * inv + c1.x); o1.y = elu1(a1.y * inv + c1.y);
    o1.z = elu1(a1.z * inv + c1.z); o1.w = elu1(a1.w * inv + c1.w);
    float4* op = (float4*)(g_act1 + (long long)d * D1);
    op[lane * 2] = o0; op[lane * 2 + 1] = o1;
}

__global__ __launch_bounds__(256) void agg2_kernel(const float* __restrict__ b2) {
    int d = (blockIdx.x * blockDim.x + threadIdx.x) >> 5;
    int lane = threadIdx.x & 31;
    if (d >= NN) return;
    float ad = g_ad2[d];
    int beg = g_rowptr[d], end = g_rowptr[d + 1];
    float z = 0.f;
    float4 a = make_float4(0.f, 0.f, 0.f, 0.f);
    for (int i = beg; i < end; i++) {
        int s = g_csrc[i];
        float w = __expf(lrelu(g_as2[s] + ad));
        z += w;
        float4 v = ((const float4*)(g_h2 + (long long)s * EMB))[lane];
        a.x += w * v.x; a.y += w * v.y; a.z += w * v.z; a.w += w * v.w;
    }
    float inv = 1.f / z;
    float4 c = ((const float4*)b2)[lane];
    float o0 = elu1(a.x * inv + c.x), o1 = elu1(a.y * inv + c.y);
    float o2 = elu1(a.z * inv + c.z), o3 = elu1(a.w * inv + c.w);
    int b = g_batch[d];
    red4(&g_pool[b * EMB + lane * 4], o0, o1, o2, o3);
}

__global__ __launch_bounds__(256) void final_div_kernel(float* __restrict__ out) {
    int i = blockIdx.x * blockDim.x + threadIdx.x;
    if (i >= NG * EMB) return;
    out[i] = g_pool[i] / fmaxf(g_cnt[i >> 7], 1.f);
}

// ---------------- launcher ----------------
extern "C" void kernel_launch(void* const* d_in, const int* in_sizes, int n_in,
                              void* d_out, int out_size)
{
    const float* x      = (const float*)d_in[0];
    const void*  ei     = d_in[1];
    const void*  batch  = d_in[3];
    const float* W1     = (const float*)d_in[4];
    const float* a_src1 = (const float*)d_in[5];
    const float* a_dst1 = (const float*)d_in[6];
    const float* b1     = (const float*)d_in[7];
    const float* W2     = (const float*)d_in[8];
    const float* a_src2 = (const float*)d_in[9];
    const float* a_dst2 = (const float*)d_in[10];
    const float* b2     = (const float*)d_in[11];
    float*       out    = (float*)d_out;

    float *p_h1, *p_act1, *p_h2, *p_as1, *p_ad1, *p_as2, *p_ad2;
    cudaGetSymbolAddress((void**)&p_h1,   g_h1);
    cudaGetSymbolAddress((void**)&p_act1, g_act1);
    cudaGetSymbolAddress((void**)&p_h2,   g_h2);
    cudaGetSymbolAddress((void**)&p_as1,  g_as1);
    cudaGetSymbolAddress((void**)&p_ad1,  g_ad1);
    cudaGetSymbolAddress((void**)&p_as2,  g_as2);
    cudaGetSymbolAddress((void**)&p_ad2,  g_ad2);

    static cudaStream_t s_side = nullptr, s_b = nullptr;
    static cudaEvent_t  ev_fork = nullptr, ev_join = nullptr, evA = nullptr, evB = nullptr;
    if (!s_side) {
        cudaStreamCreateWithFlags(&s_side, cudaStreamNonBlocking);
        cudaStreamCreateWithFlags(&s_b,    cudaStreamNonBlocking);
        cudaEventCreateWithFlags(&ev_fork, cudaEventDisableTiming);
        cudaEventCreateWithFlags(&ev_join, cudaEventDisableTiming);
        cudaEventCreateWithFlags(&evA,     cudaEventDisableTiming);
        cudaEventCreateWithFlags(&evB,     cudaEventDisableTiming);
    }

    // fork: CSR build concurrent with GEMM1
    cudaEventRecord(ev_fork, 0);
    cudaStreamWaitEvent(s_side, ev_fork, 0);
    prep_kernel<<<(NET + 255) / 256, 256, 0, s_side>>>(ei, batch);
    deg_kernel<<<(NET + 255) / 256, 256, 0, s_side>>>();
    scan_kernel<<<1, 1024, 0, s_side>>>();
    fill_kernel<<<(NET + 255) / 256, 256, 0, s_side>>>();
    cudaEventRecord(ev_join, s_side);

    // layer 1 GEMM (+fused alpha dots)
    gemm_kernel<<<dim3((NN + 127) / 128, D1 / 128), 256>>>(
        x, W1, p_h1, NN, D1, IND, 0, a_src1, a_dst1, p_as1, p_ad1, 1);

    // join CSR, then pipelined agg1 / GEMM2 halves:
    //   main: agg1_A -> gemm2_A -> (wait B) gemm2_B -> agg2
    //   s_b : (after agg1_A) agg1_B   — L2-bound, overlaps FMA-bound gemm2_A
    cudaStreamWaitEvent(0, ev_join, 0);
    agg1_kernel<<<(SPLIT + 7) / 8, 256>>>(b1, 0, SPLIT);
    cudaEventRecord(evA, 0);
    cudaStreamWaitEvent(s_b, evA, 0);
    agg1_kernel<<<((NN - SPLIT) + 7) / 8, 256, 0, s_b>>>(b1, SPLIT, NN);
    cudaEventRecord(evB, s_b);

    gemm_kernel<<<dim3(SPLIT / 128, EMB / 128), 256>>>(
        p_act1, W2, p_h2, SPLIT, EMB, D1, 0, a_src2, a_dst2, p_as2, p_ad2, 0);
    cudaStreamWaitEvent(0, evB, 0);
    gemm_kernel<<<dim3((NN - SPLIT + 127) / 128, EMB / 128), 256>>>(
        p_act1, W2, p_h2, NN, EMB, D1, SPLIT, a_src2, a_dst2, p_as2, p_ad2, 0);

    agg2_kernel<<<(NN + 7) / 8, 256>>>(b2);
    final_div_kernel<<<(NG * EMB + 255) / 256, 256>>>(out);
}

// round 11
// speedup vs baseline: 1.1473x; 1.1473x over previous
#include <cuda_runtime.h>
#include <cuda_bf16.h>

#define NN 50000
#define NE 800000
#define NET (NE + NN)
#define HEADS 4
#define HID 64
#define D1 256            // HEADS*HID
#define IND 128
#define EMB 128
#define NG 64

typedef unsigned long long ull;

// ---------------- scratch ----------------
__device__ __align__(16) __nv_bfloat16 g_h1[(size_t)NN * D1];   // bf16 messages L1
__device__ __align__(16) float         g_act1[(size_t)NN * D1]; // fp32 (gemm2 input)
__device__ __align__(16) __nv_bfloat16 g_h2[(size_t)NN * EMB];  // bf16 messages L2
__device__ __align__(16) float g_as1[NN * HEADS];
__device__ __align__(16) float g_ad1[NN * HEADS];
__device__ __align__(16) float g_as2[NN];
__device__ __align__(16) float g_ad2[NN];
__device__ __align__(16) float g_pool[NG * EMB];
__device__ __align__(16) float g_cnt[NG];
__device__ __align__(16) int   g_src[NET];
__device__ __align__(16) int   g_dst[NET];
__device__ __align__(16) int   g_batch[NN];
__device__ __align__(16) int   g_rowptr[NN + 1];
__device__ __align__(16) int   g_wp[NN];
__device__ __align__(16) int   g_csrc[NET];

// ---------------- helpers ----------------
__device__ __forceinline__ float elu1(float x)  { return x > 0.f ? x : expm1f(x); }
__device__ __forceinline__ float lrelu(float x) { return x > 0.f ? x : 0.2f * x; }

__device__ __forceinline__ void red4(float* p, float a, float b, float c, float d) {
    asm volatile("red.global.add.v4.f32 [%0], {%1, %2, %3, %4};"
                 :: "l"(p), "f"(a), "f"(b), "f"(c), "f"(d) : "memory");
}
__device__ __forceinline__ void ffma2(ull& d, ull a, ull b) {
    asm("fma.rn.f32x2 %0, %1, %2, %0;" : "+l"(d) : "l"(a), "l"(b));
}
__device__ __forceinline__ ull pack2(float lo, float hi) {
    ull r; asm("mov.b64 %0, {%1, %2};" : "=l"(r) : "f"(lo), "f"(hi)); return r;
}
__device__ __forceinline__ void unpack2(float& lo, float& hi, ull v) {
    asm("mov.b64 {%0, %1}, %2;" : "=f"(lo), "=f"(hi) : "l"(v));
}
// pack two fp32 -> bf16x2 (lo in bits[0:16), hi in [16:32))
__device__ __forceinline__ unsigned bfpack(float lo, float hi) {
    unsigned r;
    asm("cvt.rn.bf16x2.f32 %0, %1, %2;" : "=r"(r) : "f"(hi), "f"(lo));
    return r;
}
// bf16x2 -> two fp32 (shift-only)
__device__ __forceinline__ float bflo(unsigned u) { return __uint_as_float(u << 16); }
__device__ __forceinline__ float bfhi(unsigned u) { return __uint_as_float(u & 0xffff0000u); }

// ---------------- prep / CSR ----------------
__global__ __launch_bounds__(256) void prep_kernel(const void* ei_raw, const void* b_raw) {
    const int*       e32 = (const int*)ei_raw;
    const long long* e64 = (const long long*)ei_raw;
    bool is64 = true;
#pragma unroll
    for (int i = 0; i < 16; i++) is64 &= (e32[2 * i + 1] == 0);

    int idx = blockIdx.x * blockDim.x + threadIdx.x;
    if (idx < NET) {
        int s, d;
        if (idx < NE) {
            if (is64) { s = (int)e64[idx]; d = (int)e64[NE + idx]; }
            else      { s = e32[idx];      d = e32[NE + idx]; }
        } else { s = d = idx - NE; }
        g_src[idx] = s;
        g_dst[idx] = d;
    }
    if (idx < NN) {
        g_batch[idx] = is64 ? (int)((const long long*)b_raw)[idx] : ((const int*)b_raw)[idx];
        g_wp[idx] = 0;
    }
    if (idx < NG * EMB) g_pool[idx] = 0.f;
    if (idx < NG)       g_cnt[idx]  = 0.f;
}

__global__ __launch_bounds__(256) void deg_kernel() {
    int idx = blockIdx.x * blockDim.x + threadIdx.x;
    if (idx < NET) atomicAdd(&g_wp[g_dst[idx]], 1);
    if (idx < NN)  atomicAdd(&g_cnt[g_batch[idx]], 1.f);
}

__global__ __launch_bounds__(1024) void scan_kernel() {
    __shared__ int part[1024];
    int t = threadIdx.x;
    const int CH = (NN + 1023) / 1024;
    int beg = t * CH, end = min(beg + CH, NN);
    int sum = 0;
    for (int i = beg; i < end; i++) sum += g_wp[i];
    part[t] = sum;
    __syncthreads();
    for (int off = 1; off < 1024; off <<= 1) {
        int v = (t >= off) ? part[t - off] : 0;
        __syncthreads();
        part[t] += v;
        __syncthreads();
    }
    int run = (t == 0) ? 0 : part[t - 1];
    for (int i = beg; i < end; i++) {
        int c = g_wp[i];
        g_rowptr[i] = run;
        g_wp[i] = run;
        run += c;
    }
    if (t == 1023) g_rowptr[NN] = run;
}

__global__ __launch_bounds__(256) void fill_kernel() {
    int e = blockIdx.x * blockDim.x + threadIdx.x;
    if (e >= NET) return;
    int pos = atomicAdd(&g_wp[g_dst[e]], 1);
    g_csrc[pos] = g_src[e];
}

// ---------------- f32x2 GEMM + fused attention-dot epilogue ----------------
// C[M,N] = A[M,K] @ B[K,N], stored bf16. BM=128, BN=128, BK=8, 256 threads,
// 8x8/thread (M-paired f32x2 accum). Dots in fp32 from the accumulators.
__global__ __launch_bounds__(256, 2) void gemm_kernel(
    const float* __restrict__ A, const float* __restrict__ B, __nv_bfloat16* __restrict__ C,
    int M, int N, int K,
    const float* __restrict__ avec, const float* __restrict__ dvec,
    float* __restrict__ as_out, float* __restrict__ ad_out, int multihead)
{
    __shared__ float As[8][132];
    __shared__ float Bs[8][132];

    int tid = threadIdx.x;
    int lane = tid & 31;
    int rowBase = blockIdx.x * 128;
    int colBase = blockIdx.y * 128;
    int tx = tid & 15;
    int ty = tid >> 4;

    ull acc[4][8];
#pragma unroll
    for (int p = 0; p < 4; p++)
#pragma unroll
        for (int j = 0; j < 8; j++) acc[p][j] = 0ull;

    int arow = rowBase + (tid >> 1);
    int akoff = (tid & 1) * 4;
    int brow = tid >> 5;
    int bcol = colBase + (tid & 31) * 4;
    int r = tid >> 1;

    for (int k0 = 0; k0 < K; k0 += 8) {
        float4 av = make_float4(0.f, 0.f, 0.f, 0.f);
        if (arow < M) av = *(const float4*)(A + (long long)arow * K + k0 + akoff);
        float4 bv = *(const float4*)(B + (long long)(k0 + brow) * N + bcol);
        As[akoff + 0][r] = av.x; As[akoff + 1][r] = av.y;
        As[akoff + 2][r] = av.z; As[akoff + 3][r] = av.w;
        *(float4*)&Bs[brow][(tid & 31) * 4] = bv;
        __syncthreads();
#pragma unroll
        for (int kk = 0; kk < 8; kk++) {
            ulonglong2 a01 = *(const ulonglong2*)&As[kk][ty * 8];
            ulonglong2 a23 = *(const ulonglong2*)&As[kk][ty * 8 + 4];
            float4 b0 = *(const float4*)&Bs[kk][tx * 8];
            float4 b1 = *(const float4*)&Bs[kk][tx * 8 + 4];
            ull rb[8];
            rb[0] = pack2(b0.x, b0.x); rb[1] = pack2(b0.y, b0.y);
            rb[2] = pack2(b0.z, b0.z); rb[3] = pack2(b0.w, b0.w);
            rb[4] = pack2(b1.x, b1.x); rb[5] = pack2(b1.y, b1.y);
            rb[6] = pack2(b1.z, b1.z); rb[7] = pack2(b1.w, b1.w);
            ull ra[4] = {a01.x, a01.y, a23.x, a23.y};
#pragma unroll
            for (int p = 0; p < 4; p++)
#pragma unroll
                for (int j = 0; j < 8; j++) ffma2(acc[p][j], ra[p], rb[j]);
        }
        __syncthreads();
    }

    // ---- epilogue: bf16 C store + fused attention dots (fp32) ----
    float4 av0 = *(const float4*)(avec + colBase + tx * 8);
    float4 av1 = *(const float4*)(avec + colBase + tx * 8 + 4);
    float4 dv0 = *(const float4*)(dvec + colBase + tx * 8);
    float4 dv1 = *(const float4*)(dvec + colBase + tx * 8 + 4);
    float ds[8], dd[8];

#pragma unroll
    for (int p = 0; p < 4; p++) {
        float lo[8], hi[8];
#pragma unroll
        for (int j = 0; j < 8; j++) unpack2(lo[j], hi[j], acc[p][j]);
        int m0 = rowBase + ty * 8 + 2 * p;
        long long cbase = (long long)m0 * N + colBase + tx * 8;
        if (m0 < M) {
            uint4 u;
            u.x = bfpack(lo[0], lo[1]); u.y = bfpack(lo[2], lo[3]);
            u.z = bfpack(lo[4], lo[5]); u.w = bfpack(lo[6], lo[7]);
            *(uint4*)(C + cbase) = u;
        }
        if (m0 + 1 < M) {
            uint4 u;
            u.x = bfpack(hi[0], hi[1]); u.y = bfpack(hi[2], hi[3]);
            u.z = bfpack(hi[4], hi[5]); u.w = bfpack(hi[6], hi[7]);
            *(uint4*)(C + cbase + N) = u;
        }
        ds[2*p]   = lo[0]*av0.x + lo[1]*av0.y + lo[2]*av0.z + lo[3]*av0.w
                  + lo[4]*av1.x + lo[5]*av1.y + lo[6]*av1.z + lo[7]*av1.w;
        dd[2*p]   = lo[0]*dv0.x + lo[1]*dv0.y + lo[2]*dv0.z + lo[3]*dv0.w
                  + lo[4]*dv1.x + lo[5]*dv1.y + lo[6]*dv1.z + lo[7]*dv1.w;
        ds[2*p+1] = hi[0]*av0.x + hi[1]*av0.y + hi[2]*av0.z + hi[3]*av0.w
                  + hi[4]*av1.x + hi[5]*av1.y + hi[6]*av1.z + hi[7]*av1.w;
        dd[2*p+1] = hi[0]*dv0.x + hi[1]*dv0.y + hi[2]*dv0.z + hi[3]*dv0.w
                  + hi[4]*dv1.x + hi[5]*dv1.y + hi[6]*dv1.z + hi[7]*dv1.w;
    }
#pragma unroll
    for (int rr = 0; rr < 8; rr++) {
        ds[rr] += __shfl_xor_sync(0xffffffffu, ds[rr], 1);
        ds[rr] += __shfl_xor_sync(0xffffffffu, ds[rr], 2);
        ds[rr] += __shfl_xor_sync(0xffffffffu, ds[rr], 4);
        dd[rr] += __shfl_xor_sync(0xffffffffu, dd[rr], 1);
        dd[rr] += __shfl_xor_sync(0xffffffffu, dd[rr], 2);
        dd[rr] += __shfl_xor_sync(0xffffffffu, dd[rr], 4);
        if (!multihead) {
            ds[rr] += __shfl_xor_sync(0xffffffffu, ds[rr], 8);
            dd[rr] += __shfl_xor_sync(0xffffffffu, dd[rr], 8);
        }
    }
    int rowb = rowBase + ty * 8;
    if (multihead) {
        if ((lane & 7) == 0) {
            int head = (colBase >> 6) + ((lane >> 3) & 1);
#pragma unroll
            for (int rr = 0; rr < 8; rr++) {
                int row = rowb + rr;
                if (row < M) {
                    as_out[row * 4 + head] = ds[rr];
                    ad_out[row * 4 + head] = dd[rr];
                }
            }
        }
    } else {
        if ((lane & 15) == 0) {
#pragma unroll
            for (int rr = 0; rr < 8; rr++) {
                int row = rowb + rr;
                if (row < M) {
                    as_out[row] = ds[rr];
                    ad_out[row] = dd[rr];
                }
            }
        }
    }
}

// ---------------- CSR aggregation (warp per dst node, bf16 messages) ----------------
__global__ __launch_bounds__(256) void agg1_kernel(const float* __restrict__ b1) {
    int d = (blockIdx.x * blockDim.x + threadIdx.x) >> 5;
    int lane = threadIdx.x & 31;
    if (d >= NN) return;
    int h = lane >> 3;
    float ad = g_ad1[d * 4 + h];
    int beg = g_rowptr[d], end = g_rowptr[d + 1];
    float z = 0.f;
    float a[8] = {0.f, 0.f, 0.f, 0.f, 0.f, 0.f, 0.f, 0.f};
    for (int i = beg; i < end; i++) {
        int s = g_csrc[i];
        float w = __expf(lrelu(g_as1[s * 4 + h] + ad));
        z += w;
        uint4 v = *(const uint4*)(g_h1 + (size_t)s * D1 + lane * 8);   // 8 bf16
        a[0] += w * bflo(v.x); a[1] += w * bfhi(v.x);
        a[2] += w * bflo(v.y); a[3] += w * bfhi(v.y);
        a[4] += w * bflo(v.z); a[5] += w * bfhi(v.z);
        a[6] += w * bflo(v.w); a[7] += w * bfhi(v.w);
    }
    float inv = 1.f / z;
    const float4* bb = (const float4*)(b1 + lane * 8);
    float4 c0 = bb[0], c1 = bb[1];
    float4 o0, o1;
    o0.x = elu1(a[0] * inv + c0.x); o0.y = elu1(a[1] * inv + c0.y);
    o0.z = elu1(a[2] * inv + c0.z); o0.w = elu1(a[3] * inv + c0.w);
    o1.x = elu1(a[4] * inv + c1.x); o1.y = elu1(a[5] * inv + c1.y);
    o1.z = elu1(a[6] * inv + c1.z); o1.w = elu1(a[7] * inv + c1.w);
    float4* op = (float4*)(g_act1 + (size_t)d * D1 + lane * 8);
    op[0] = o0; op[1] = o1;
}

__global__ __launch_bounds__(256) void agg2_kernel(const float* __restrict__ b2) {
    int d = (blockIdx.x * blockDim.x + threadIdx.x) >> 5;
    int lane = threadIdx.x & 31;
    if (d >= NN) return;
    float ad = g_ad2[d];
    int beg = g_rowptr[d], end = g_rowptr[d + 1];
    float z = 0.f;
    float a[4] = {0.f, 0.f, 0.f, 0.f};
    for (int i = beg; i < end; i++) {
        int s = g_csrc[i];
        float w = __expf(lrelu(g_as2[s] + ad));
        z += w;
        uint2 v = *(const uint2*)(g_h2 + (size_t)s * EMB + lane * 4);  // 4 bf16
        a[0] += w * bflo(v.x); a[1] += w * bfhi(v.x);
        a[2] += w * bflo(v.y); a[3] += w * bfhi(v.y);
    }
    float inv = 1.f / z;
    float4 c = ((const float4*)b2)[lane];
    float o0 = elu1(a[0] * inv + c.x), o1 = elu1(a[1] * inv + c.y);
    float o2 = elu1(a[2] * inv + c.z), o3 = elu1(a[3] * inv + c.w);
    int b = g_batch[d];
    red4(&g_pool[b * EMB + lane * 4], o0, o1, o2, o3);
}

__global__ __launch_bounds__(256) void final_div_kernel(float* __restrict__ out) {
    int i = blockIdx.x * blockDim.x + threadIdx.x;
    if (i >= NG * EMB) return;
    out[i] = g_pool[i] / fmaxf(g_cnt[i >> 7], 1.f);
}

// ---------------- launcher ----------------
extern "C" void kernel_launch(void* const* d_in, const int* in_sizes, int n_in,
                              void* d_out, int out_size)
{
    const float* x      = (const float*)d_in[0];
    const void*  ei     = d_in[1];
    const void*  batch  = d_in[3];
    const float* W1     = (const float*)d_in[4];
    const float* a_src1 = (const float*)d_in[5];
    const float* a_dst1 = (const float*)d_in[6];
    const float* b1     = (const float*)d_in[7];
    const float* W2     = (const float*)d_in[8];
    const float* a_src2 = (const float*)d_in[9];
    const float* a_dst2 = (const float*)d_in[10];
    const float* b2     = (const float*)d_in[11];
    float*       out    = (float*)d_out;

    __nv_bfloat16 *p_h1, *p_h2;
    float *p_act1, *p_as1, *p_ad1, *p_as2, *p_ad2;
    cudaGetSymbolAddress((void**)&p_h1,   g_h1);
    cudaGetSymbolAddress((void**)&p_act1, g_act1);
    cudaGetSymbolAddress((void**)&p_h2,   g_h2);
    cudaGetSymbolAddress((void**)&p_as1,  g_as1);
    cudaGetSymbolAddress((void**)&p_ad1,  g_ad1);
    cudaGetSymbolAddress((void**)&p_as2,  g_as2);
    cudaGetSymbolAddress((void**)&p_ad2,  g_ad2);

    static cudaStream_t s_side = nullptr;
    static cudaEvent_t  ev_fork = nullptr, ev_join = nullptr;
    if (!s_side) {
        cudaStreamCreateWithFlags(&s_side, cudaStreamNonBlocking);
        cudaEventCreateWithFlags(&ev_fork, cudaEventDisableTiming);
        cudaEventCreateWithFlags(&ev_join, cudaEventDisableTiming);
    }

    // fork: CSR build concurrent with GEMM1
    cudaEventRecord(ev_fork, 0);
    cudaStreamWaitEvent(s_side, ev_fork, 0);
    prep_kernel<<<(NET + 255) / 256, 256, 0, s_side>>>(ei, batch);
    deg_kernel<<<(NET + 255) / 256, 256, 0, s_side>>>();
    scan_kernel<<<1, 1024, 0, s_side>>>();
    fill_kernel<<<(NET + 255) / 256, 256, 0, s_side>>>();
    cudaEventRecord(ev_join, s_side);

    // layer 1 GEMM (+fused alpha dots)
    gemm_kernel<<<dim3((NN + 127) / 128, D1 / 128), 256>>>(
        x, W1, p_h1, NN, D1, IND, a_src1, a_dst1, p_as1, p_ad1, 1);

    // join CSR, then serial agg1 -> gemm2 -> agg2 (R9 proven schedule)
    cudaStreamWaitEvent(0, ev_join, 0);
    agg1_kernel<<<(NN + 7) / 8, 256>>>(b1);

    gemm_kernel<<<dim3((NN + 127) / 128, EMB / 128), 256>>>(
        p_act1, W2, p_h2, NN, EMB, D1, a_src2, a_dst2, p_as2, p_ad2, 0);
    agg2_kernel<<<(NN + 7) / 8, 256>>>(b2);

    final_div_kernel<<<(NG * EMB + 255) / 256, 256>>>(out);
}